// round 15
// baseline (speedup 1.0000x reference)
#include <cuda_runtime.h>
#include <cuda_fp16.h>
#include <cstdint>
#include <math.h>

#define Bk 8
#define Ck 64
#define Hk 128
#define Wk 128
#define NPIX (Hk*Wk)                 // 16384
#define PLANE (Ck*NPIX)              // 1,048,576 per batch
#define TENSOR (Bk*PLANE)            // 8,388,608 elements
#define QPLANE (32*NPIX)             // half2 per batch (quad layout)

// ---------------------------------------------------------------------------
// Scratch (device globals; no allocation)
// ---------------------------------------------------------------------------
__device__ float   g_tmp_edge[TENSOR];          // fp32 tmp edge (guide for stage2)
__device__ __half  g_kern[Bk * 9 * NPIX];       // adaptive kernel field (fp16)
__device__ float   g_fields[Bk * 5 * NPIX];
// quad layout: [b][g=ch/8][pix][4 half2 (tq)]  -> index ((b*8+g)*NPIX+pix)*4+tq
__device__ __half2 g_xh[Bk * QPLANE];
__device__ __half2 g_eh[Bk * QPLANE];
__device__ __half2 g_tsh[Bk * QPLANE];
__device__ __half2 g_teh[Bk * QPLANE];
// packed fp16 weight fragments: [set 4][tap 9][kh 2][kc 2][nc 8][lane 32][reg 2]
__device__ uint32_t g_wpk[4 * 9 * 2048];

// ---------------------------------------------------------------------------
#define MMAF16(c, A0, A1, A2, A3, B0, B1)                                    \
    asm volatile(                                                            \
        "mma.sync.aligned.m16n8k16.row.col.f32.f16.f16.f32 "                 \
        "{%0,%1,%2,%3},{%4,%5,%6,%7},{%8,%9},{%0,%1,%2,%3};"                 \
        : "+f"((c)[0]), "+f"((c)[1]), "+f"((c)[2]), "+f"((c)[3])             \
        : "r"(A0), "r"(A1), "r"(A2), "r"(A3), "r"(B0), "r"(B1))

// ---------------------------------------------------------------------------
// Weight prep (single fp16 term): [kh][kc][nc][lane][reg]
// ---------------------------------------------------------------------------
__global__ void prep_weights(const float* __restrict__ w0,
                             const float* __restrict__ w1,
                             const float* __restrict__ w2,
                             const float* __restrict__ w3) {
    int idx = blockIdx.x * blockDim.x + threadIdx.x;
    if (idx >= 4 * 9 * 2048) return;
    int s    = idx / 18432;
    int rem  = idx % 18432;
    int p    = rem / 2048;
    int rem2 = rem % 2048;
    int kh   = (rem2 >> 10) & 1;
    int kc   = (rem2 >> 9) & 1;
    int nc   = (rem2 >> 6) & 7;
    int l    = (rem2 >> 1) & 31;
    int r    = rem2 & 1;

    int o = nc * 8 + (l >> 2);
    int k = kh * 32 + kc * 16 + (l & 3) * 2 + r * 8;

    const float* w = (s == 0) ? w0 : (s == 1) ? w1 : (s == 2) ? w2 : w3;
    float2 v;
    v.x = w[(o * 64 + k) * 9 + p];
    v.y = w[(o * 64 + k + 1) * 9 + p];
    __half2 h2 = __float22half2_rn(v);
    g_wpk[idx] = *(uint32_t*)&h2;
}

// ---------------------------------------------------------------------------
// Split fp32 NCHW -> quad-interleaved half2. blockIdx.y: 0=x, 1=edge
// ---------------------------------------------------------------------------
__global__ void __launch_bounds__(256)
split_kernel(const float* __restrict__ a, const float* __restrict__ b,
             __half2* __restrict__ ah, __half2* __restrict__ bh) {
    int idx = blockIdx.x * 256 + threadIdx.x;       // over Bk*8*NPIX
    const float* src = blockIdx.y ? b : a;
    __half2* dst = blockIdx.y ? bh : ah;
    int pix = idx & (NPIX - 1);
    int g   = (idx >> 14) & 7;
    int bb  = idx >> 17;
    const float* s = src + ((size_t)(bb * 64 + g * 8)) * NPIX + pix;
    __half2 q[4];
#pragma unroll
    for (int t = 0; t < 4; t++) {
        float2 v;
        v.x = __ldg(s + (size_t)(t * 2) * NPIX);
        v.y = __ldg(s + (size_t)(t * 2 + 1) * NPIX);
        q[t] = __float22half2_rn(v);
    }
    *(uint4*)(dst + (size_t)idx * 4) = *(uint4*)q;
}

// ---------------------------------------------------------------------------
// Pass A: per-pixel fields via warp shuffles (no smem, no barriers).
// sq; dot(0,1); dot(1,e), e=-1,0,1. grid (Hk, Bk), 128 thr.
// ---------------------------------------------------------------------------
__global__ void __launch_bounds__(128)
field_kernel(const float* __restrict__ g, float* __restrict__ F) {
    const int h    = blockIdx.x;
    const int bb   = blockIdx.y;
    const int w    = threadIdx.x;
    const int lane = w & 31;

    float sq = 0.f, d01 = 0.f, d1m = 0.f, d10 = 0.f, d1p = 0.f;

    const float* row0 = g + bb * PLANE + h * Wk;
    const bool row1ok = (h + 1 < Hk);
    const float* row1 = row0 + Wk;

    const bool bn = (lane == 31);                 // needs w+1 values
    const bool bp = (lane == 0) && (w > 0);       // needs w-1 value (row1)
    const bool wn_ok = (w + 1 < Wk);

#pragma unroll 4
    for (int c = 0; c < 64; c++) {
        const size_t co = (size_t)c * NPIX;
        float v0 = __ldg(row0 + co + w);
        float v1 = row1ok ? __ldg(row1 + co + w) : 0.f;

        float v0n = 0.f, v1n = 0.f, v1p = 0.f;
        if (bn && wn_ok) {
            v0n = __ldg(row0 + co + w + 1);
            if (row1ok) v1n = __ldg(row1 + co + w + 1);
        }
        if (bp && row1ok) v1p = __ldg(row1 + co + w - 1);

        float r  = __shfl_down_sync(0xffffffffu, v0, 1);
        float br = __shfl_down_sync(0xffffffffu, v1, 1);
        float bl = __shfl_up_sync(0xffffffffu, v1, 1);
        if (lane == 31) { r = v0n; br = v1n; }
        if (lane == 0)  { bl = v1p; }

        sq  += v0 * v0;
        d01 += v0 * r;
        d1m += v0 * bl;
        d10 += v0 * v1;
        d1p += v0 * br;
    }

    float* Fb = F + bb * 5 * NPIX + h * Wk + w;
    Fb[0 * NPIX] = sq;
    Fb[1 * NPIX] = d01;
    Fb[2 * NPIX] = d1m;
    Fb[3 * NPIX] = d10;
    Fb[4 * NPIX] = d1p;
}

// ---------------------------------------------------------------------------
// Pass B: kern[b][p][h][w] = exp(-0.5*(sq_nb + sq_c - 2*dot)), fp16 out.
// ---------------------------------------------------------------------------
__global__ void __launch_bounds__(128)
kern_assemble_kernel(const float* __restrict__ F, __half* __restrict__ kout) {
    const int h  = blockIdx.x;
    const int bb = blockIdx.y;
    const int w  = threadIdx.x;

    const float* Fb = F + bb * 5 * NPIX;
    const float sqc = Fb[h * Wk + w];

    __half* ko = kout + (bb * 9) * NPIX + h * Wk + w;

#pragma unroll
    for (int p = 0; p < 9; p++) {
        if (p == 4) { ko[4 * NPIX] = __float2half(1.0f); continue; }
        const int dy = p / 3 - 1, dx = p % 3 - 1;
        const int row = h + dy, col = w + dx;
        const bool inb = (row >= 0) && (row < Hk) && (col >= 0) && (col < Wk);
        float sqn = 0.f, dot = 0.f;
        if (inb) {
            sqn = Fb[row * Wk + col];
            if (dy == 0) {
                dot = (dx == 1) ? Fb[NPIX + h * Wk + w]
                                : Fb[NPIX + h * Wk + (w - 1)];
            } else if (dy == 1) {
                dot = Fb[(3 + dx) * NPIX + h * Wk + w];
            } else {
                dot = Fb[(3 - dx) * NPIX + (h - 1) * Wk + col];
            }
        }
        float d2 = sqn + sqc - 2.f * dot;
        ko[p * NPIX] = __float2half(__expf(-0.5f * d2));
    }
}

// ---------------------------------------------------------------------------
// HMMA conv (R14, unchanged): quad-interleaved x, single fp16 term.
// Block = 2 image rows (M=256 pix, N=64 cout), 256 thr / 8 warps.
// ---------------------------------------------------------------------------
__global__ void __launch_bounds__(256, 2)
conv3x3_hmma_kernel(const __half2* __restrict__ xin0,
                    const __half* __restrict__ kern0,  // null => plain
                    const uint32_t* __restrict__ wt0,
                    const float* __restrict__ bias0,
                    const float* __restrict__ resid0,
                    __half2* __restrict__ outh0,
                    float* __restrict__ outf0,
                    const __half2* __restrict__ xin1,
                    const uint32_t* __restrict__ wt1,
                    const float* __restrict__ bias1,
                    const float* __restrict__ resid1,
                    __half2* __restrict__ outh1,
                    float* __restrict__ outf1,
                    int do_relu) {
    const int h0 = blockIdx.x * 2;
    const int bb = blockIdx.y;
    const int z  = blockIdx.z;

    const __half2*  xin   = z ? xin1 : xin0;
    const __half*   kern  = z ? nullptr : kern0;
    const uint32_t* wt    = z ? wt1 : wt0;
    const float*    bias  = z ? bias1 : bias0;
    const float*    resid = z ? resid1 : resid0;
    __half2*        outh  = z ? outh1 : outh0;
    float*          outf  = z ? outf1 : outf0;

    const int tid  = threadIdx.x;
    const int warp = tid >> 5;
    const int lane = tid & 31;
    const int gq   = lane >> 2;
    const int tq   = lane & 3;
    const int wr   = warp >> 2;
    const int c0   = (warp & 3) << 5;
    const int row_out = h0 + wr;

    int pixc[2][2];
    pixc[0][0] = c0 + gq;      pixc[0][1] = c0 + gq + 8;
    pixc[1][0] = c0 + 16 + gq; pixc[1][1] = c0 + 24 + gq;

    float acc[2][8][4];
#pragma unroll
    for (int mh = 0; mh < 2; mh++)
#pragma unroll
        for (int n = 0; n < 8; n++)
#pragma unroll
            for (int i = 0; i < 4; i++) acc[mh][n][i] = 0.f;

    const __half2* xb = xin + (size_t)bb * QPLANE;

    for (int p = 0; p < 9; p++) {
        const int dy = p / 3 - 1, dx = p % 3 - 1;
        const int row = row_out + dy;
        if (row < 0 || row >= Hk) continue;

        __half2 kv2[2][2];
        if (kern) {
            const __half* kb = kern + ((bb * 9 + p) * Hk + row_out) * Wk;
            kv2[0][0] = __half2half2(__ldg(kb + pixc[0][0]));
            kv2[0][1] = __half2half2(__ldg(kb + pixc[0][1]));
            kv2[1][0] = __half2half2(__ldg(kb + pixc[1][0]));
            kv2[1][1] = __half2half2(__ldg(kb + pixc[1][1]));
        }

        const __half2* xrow = xb + (size_t)(row * Wk) * 4 + tq;

#pragma unroll
        for (int kh2 = 0; kh2 < 2; kh2++) {
            const uint2* bw =
                (const uint2*)(wt + p * 2048 + kh2 * 1024) + lane;

#pragma unroll
            for (int kc = 0; kc < 2; kc++) {
                uint32_t f[2][4];
#pragma unroll
                for (int mh = 0; mh < 2; mh++)
#pragma unroll
                    for (int kk = 0; kk < 2; kk++)
#pragma unroll
                        for (int rr = 0; rr < 2; rr++) {
                            const int g = kh2 * 4 + kc * 2 + kk;
                            const int col = pixc[mh][rr] + dx;
                            const bool ok = (unsigned)col < 128u;
                            __half2 v = ok
                                ? __ldg(xrow + ((size_t)g * NPIX + col) * 4)
                                : __half2(__float2half2_rn(0.f));
                            if (kern) v = __hmul2(v, kv2[mh][rr]);
                            f[mh][rr + kk * 2] = *(uint32_t*)&v;
                        }

#pragma unroll
                for (int nc = 0; nc < 8; nc++) {
                    uint2 b = __ldg(bw + (kc * 8 + nc) * 32);
                    MMAF16(acc[0][nc], f[0][0], f[0][1], f[0][2], f[0][3],
                           b.x, b.y);
                    MMAF16(acc[1][nc], f[1][0], f[1][1], f[1][2], f[1][3],
                           b.x, b.y);
                }
            }
        }
    }

    // epilogue
    const int rowoff0 = row_out * Wk;
#pragma unroll
    for (int mh = 0; mh < 2; mh++) {
#pragma unroll
        for (int nc = 0; nc < 8; nc++) {
            int o0 = nc * 8 + tq * 2;
            float bv0 = __ldg(bias + o0);
            float bv1 = __ldg(bias + o0 + 1);
            float v00 = acc[mh][nc][0] + bv0;
            float v01 = acc[mh][nc][1] + bv1;
            float v10 = acc[mh][nc][2] + bv0;
            float v11 = acc[mh][nc][3] + bv1;
            if (do_relu) {
                v00 = fmaxf(v00, 0.f); v01 = fmaxf(v01, 0.f);
                v10 = fmaxf(v10, 0.f); v11 = fmaxf(v11, 0.f);
            }
            if (outh) {
                __half2* oh = outh + ((size_t)(bb * 8 + nc) * NPIX + rowoff0) * 4 + tq;
                float2 p0; p0.x = v00; p0.y = v01;
                float2 p1; p1.x = v10; p1.y = v11;
                oh[(size_t)pixc[mh][0] * 4] = __float22half2_rn(p0);
                oh[(size_t)pixc[mh][1] * 4] = __float22half2_rn(p1);
            }
            if (outf) {
                int i00 = (bb * Ck + o0) * NPIX + rowoff0 + pixc[mh][0];
                if (resid) {
                    v00 += resid[i00];
                    v01 += resid[i00 + NPIX];
                    v10 += resid[i00 + 8];
                    v11 += resid[i00 + NPIX + 8];
                }
                outf[i00] = v00;
                outf[i00 + NPIX] = v01;
                outf[i00 + 8] = v10;
                outf[i00 + NPIX + 8] = v11;
            }
        }
    }
}

// ---------------------------------------------------------------------------
extern "C" void kernel_launch(void* const* d_in, const int* in_sizes, int n_in,
                              void* d_out, int out_size) {
    const float* x      = (const float*)d_in[0];
    const float* edge   = (const float*)d_in[1];
    const float* w_pac1 = (const float*)d_in[2];
    const float* b_pac1 = (const float*)d_in[3];
    const float* w_pac2 = (const float*)d_in[4];
    const float* b_pac2 = (const float*)d_in[5];
    const float* w_e1   = (const float*)d_in[6];
    const float* b_e1   = (const float*)d_in[7];
    const float* w_e2   = (const float*)d_in[8];
    const float* b_e2   = (const float*)d_in[9];

    float* out_sr   = (float*)d_out;
    float* out_edge = out_sr + TENSOR;

    float *p_tmp_edge, *p_fields;
    __half* p_kern;
    __half2 *p_xh, *p_eh, *p_tsh, *p_teh;
    uint32_t* p_wpk;
    cudaGetSymbolAddress((void**)&p_tmp_edge, g_tmp_edge);
    cudaGetSymbolAddress((void**)&p_kern, g_kern);
    cudaGetSymbolAddress((void**)&p_fields, g_fields);
    cudaGetSymbolAddress((void**)&p_xh, g_xh);
    cudaGetSymbolAddress((void**)&p_eh, g_eh);
    cudaGetSymbolAddress((void**)&p_tsh, g_tsh);
    cudaGetSymbolAddress((void**)&p_teh, g_teh);
    cudaGetSymbolAddress((void**)&p_wpk, g_wpk);

    prep_weights<<<(4 * 9 * 2048 + 255) / 256, 256>>>(w_pac1, w_pac2, w_e1, w_e2);

    {
        dim3 sgrid((Bk * 8 * NPIX + 255) / 256, 2);
        split_kernel<<<sgrid, 256>>>(x, edge, p_xh, p_eh);
    }

    dim3 kgrid(Hk, Bk);
    dim3 cgrid(Hk / 2, Bk, 2);
    const int WS = 9 * 2048;

    // stage 1: kern(edge); z=0 pac(x) -> tsh, z=1 conv(edge) -> teh + fp32
    field_kernel<<<kgrid, 128>>>(edge, p_fields);
    kern_assemble_kernel<<<kgrid, 128>>>(p_fields, p_kern);
    conv3x3_hmma_kernel<<<cgrid, 256>>>(
        p_xh, p_kern, p_wpk + 0 * WS, b_pac1, nullptr, p_tsh, nullptr,
        p_eh,         p_wpk + 2 * WS, b_e1,   nullptr, p_teh, p_tmp_edge, 1);

    // stage 2: kern(tmp_edge); z=0 pac(tsh)+x -> out_sr, z=1 conv(teh)+edge
    field_kernel<<<kgrid, 128>>>(p_tmp_edge, p_fields);
    kern_assemble_kernel<<<kgrid, 128>>>(p_fields, p_kern);
    conv3x3_hmma_kernel<<<cgrid, 256>>>(
        p_tsh, p_kern, p_wpk + 1 * WS, b_pac2, x,    nullptr, out_sr,
        p_teh,         p_wpk + 3 * WS, b_e2,   edge, nullptr, out_edge, 0);
}

// round 16
// speedup vs baseline: 1.0373x; 1.0373x over previous
#include <cuda_runtime.h>
#include <cuda_fp16.h>
#include <cstdint>
#include <math.h>

#define Bk 8
#define Ck 64
#define Hk 128
#define Wk 128
#define NPIX (Hk*Wk)                 // 16384
#define PLANE (Ck*NPIX)              // 1,048,576 per batch
#define TENSOR (Bk*PLANE)            // 8,388,608 elements
#define QPLANE (32*NPIX)             // half2 per batch (quad layout)

// ---------------------------------------------------------------------------
// Scratch (device globals; no allocation)
// ---------------------------------------------------------------------------
__device__ float   g_tmp_edge[TENSOR];          // fp32 tmp edge (guide for stage2)
__device__ __half  g_kern[Bk * 9 * NPIX];       // adaptive kernel field (fp16)
__device__ float   g_fields[Bk * 5 * NPIX];
// quad layout: [b][g=ch/8][pix][4 half2 (tq)]  -> index ((b*8+g)*NPIX+pix)*4+tq
__device__ __half2 g_xh[Bk * QPLANE];
__device__ __half2 g_eh[Bk * QPLANE];
__device__ __half2 g_tsh[Bk * QPLANE];
__device__ __half2 g_teh[Bk * QPLANE];
// packed fp16 weight fragments: [set 4][tap 9][kh 2][kc 2][nc 8][lane 32][reg 2]
__device__ uint32_t g_wpk[4 * 9 * 2048];

// ---------------------------------------------------------------------------
#define MMAF16(c, A0, A1, A2, A3, B0, B1)                                    \
    asm volatile(                                                            \
        "mma.sync.aligned.m16n8k16.row.col.f32.f16.f16.f32 "                 \
        "{%0,%1,%2,%3},{%4,%5,%6,%7},{%8,%9},{%0,%1,%2,%3};"                 \
        : "+f"((c)[0]), "+f"((c)[1]), "+f"((c)[2]), "+f"((c)[3])             \
        : "r"(A0), "r"(A1), "r"(A2), "r"(A3), "r"(B0), "r"(B1))

// ---------------------------------------------------------------------------
// Weight prep (single fp16 term): [kh][kc][nc][lane][reg]
// ---------------------------------------------------------------------------
__global__ void prep_weights(const float* __restrict__ w0,
                             const float* __restrict__ w1,
                             const float* __restrict__ w2,
                             const float* __restrict__ w3) {
    int idx = blockIdx.x * blockDim.x + threadIdx.x;
    if (idx >= 4 * 9 * 2048) return;
    int s    = idx / 18432;
    int rem  = idx % 18432;
    int p    = rem / 2048;
    int rem2 = rem % 2048;
    int kh   = (rem2 >> 10) & 1;
    int kc   = (rem2 >> 9) & 1;
    int nc   = (rem2 >> 6) & 7;
    int l    = (rem2 >> 1) & 31;
    int r    = rem2 & 1;

    int o = nc * 8 + (l >> 2);
    int k = kh * 32 + kc * 16 + (l & 3) * 2 + r * 8;

    const float* w = (s == 0) ? w0 : (s == 1) ? w1 : (s == 2) ? w2 : w3;
    float2 v;
    v.x = w[(o * 64 + k) * 9 + p];
    v.y = w[(o * 64 + k + 1) * 9 + p];
    __half2 h2 = __float22half2_rn(v);
    g_wpk[idx] = *(uint32_t*)&h2;
}

// ---------------------------------------------------------------------------
// Split fp32 NCHW -> quad-interleaved half2. blockIdx.y: 0=x, 1=edge
// ---------------------------------------------------------------------------
__global__ void __launch_bounds__(256)
split_kernel(const float* __restrict__ a, const float* __restrict__ b,
             __half2* __restrict__ ah, __half2* __restrict__ bh) {
    int idx = blockIdx.x * 256 + threadIdx.x;       // over Bk*8*NPIX
    const float* src = blockIdx.y ? b : a;
    __half2* dst = blockIdx.y ? bh : ah;
    int pix = idx & (NPIX - 1);
    int g   = (idx >> 14) & 7;
    int bb  = idx >> 17;
    const float* s = src + ((size_t)(bb * 64 + g * 8)) * NPIX + pix;
    __half2 q[4];
#pragma unroll
    for (int t = 0; t < 4; t++) {
        float2 v;
        v.x = __ldg(s + (size_t)(t * 2) * NPIX);
        v.y = __ldg(s + (size_t)(t * 2 + 1) * NPIX);
        q[t] = __float22half2_rn(v);
    }
    *(uint4*)(dst + (size_t)idx * 4) = *(uint4*)q;
}

// ---------------------------------------------------------------------------
// Pass A: per-pixel fields, 2 output rows per block.
// sq; dot(0,1); dot(1,e), e=-1,0,1. grid (Hk/2, Bk), 256 thr.
// smem: 8 ch x 3 rows (h0..h0+2) x 132 cols.
// ---------------------------------------------------------------------------
__global__ void __launch_bounds__(256)
field_kernel(const float* __restrict__ g, float* __restrict__ F) {
    const int h0 = blockIdx.x * 2;
    const int bb = blockIdx.y;
    const int tid = threadIdx.x;
    const int r  = tid >> 7;        // output row within block: 0/1
    const int w  = tid & 127;

    __shared__ float s[8][3][132];

    float sq = 0.f, d01 = 0.f, d1m = 0.f, d10 = 0.f, d1p = 0.f;

    const float* gb = g + bb * PLANE;

    for (int c0 = 0; c0 < 64; c0 += 8) {
        if (c0) __syncthreads();
        // stage 8 channels x 3 rows x 128 cols (12 loads/thread)
#pragma unroll
        for (int n = 0; n < 12; n++) {
            int i   = tid + n * 256;          // 0..3071
            int col = i & 127;
            int rr  = (i >> 7) % 3;
            int ch  = i / 384;
            int grow = h0 + rr;
            float v = (grow < Hk) ? gb[(c0 + ch) * NPIX + grow * Wk + col] : 0.f;
            s[ch][rr][col + 1] = v;
        }
        // zero halo columns (8 ch x 3 rows x 2 = 48)
        if (tid < 48) {
            int ch  = tid / 6;
            int rem = tid - ch * 6;
            int rr  = rem >> 1;
            int sc  = (rem & 1) ? 129 : 0;
            s[ch][rr][sc] = 0.f;
        }
        __syncthreads();
#pragma unroll
        for (int ch = 0; ch < 8; ch++) {
            float c  = s[ch][r][w + 1];
            float rt = s[ch][r][w + 2];
            float bl = s[ch][r + 1][w];
            float bc = s[ch][r + 1][w + 1];
            float br = s[ch][r + 1][w + 2];
            sq  += c * c;
            d01 += c * rt;
            d1m += c * bl;
            d10 += c * bc;
            d1p += c * br;
        }
    }

    const int h = h0 + r;
    float* Fb = F + bb * 5 * NPIX + h * Wk + w;
    Fb[0 * NPIX] = sq;
    Fb[1 * NPIX] = d01;
    Fb[2 * NPIX] = d1m;
    Fb[3 * NPIX] = d10;
    Fb[4 * NPIX] = d1p;
}

// ---------------------------------------------------------------------------
// Pass B: kern[b][p][h][w] = exp(-0.5*(sq_nb + sq_c - 2*dot)), fp16 out.
// ---------------------------------------------------------------------------
__global__ void __launch_bounds__(128)
kern_assemble_kernel(const float* __restrict__ F, __half* __restrict__ kout) {
    const int h  = blockIdx.x;
    const int bb = blockIdx.y;
    const int w  = threadIdx.x;

    const float* Fb = F + bb * 5 * NPIX;
    const float sqc = Fb[h * Wk + w];

    __half* ko = kout + (bb * 9) * NPIX + h * Wk + w;

#pragma unroll
    for (int p = 0; p < 9; p++) {
        if (p == 4) { ko[4 * NPIX] = __float2half(1.0f); continue; }
        const int dy = p / 3 - 1, dx = p % 3 - 1;
        const int row = h + dy, col = w + dx;
        const bool inb = (row >= 0) && (row < Hk) && (col >= 0) && (col < Wk);
        float sqn = 0.f, dot = 0.f;
        if (inb) {
            sqn = Fb[row * Wk + col];
            if (dy == 0) {
                dot = (dx == 1) ? Fb[NPIX + h * Wk + w]
                                : Fb[NPIX + h * Wk + (w - 1)];
            } else if (dy == 1) {
                dot = Fb[(3 + dx) * NPIX + h * Wk + w];
            } else {
                dot = Fb[(3 - dx) * NPIX + (h - 1) * Wk + col];
            }
        }
        float d2 = sqn + sqc - 2.f * dot;
        ko[p * NPIX] = __float2half(__expf(-0.5f * d2));
    }
}

// ---------------------------------------------------------------------------
// HMMA conv (R14, unchanged): quad-interleaved x, single fp16 term.
// Block = 2 image rows (M=256 pix, N=64 cout), 256 thr / 8 warps.
// ---------------------------------------------------------------------------
__global__ void __launch_bounds__(256, 2)
conv3x3_hmma_kernel(const __half2* __restrict__ xin0,
                    const __half* __restrict__ kern0,  // null => plain
                    const uint32_t* __restrict__ wt0,
                    const float* __restrict__ bias0,
                    const float* __restrict__ resid0,
                    __half2* __restrict__ outh0,
                    float* __restrict__ outf0,
                    const __half2* __restrict__ xin1,
                    const uint32_t* __restrict__ wt1,
                    const float* __restrict__ bias1,
                    const float* __restrict__ resid1,
                    __half2* __restrict__ outh1,
                    float* __restrict__ outf1,
                    int do_relu) {
    const int h0 = blockIdx.x * 2;
    const int bb = blockIdx.y;
    const int z  = blockIdx.z;

    const __half2*  xin   = z ? xin1 : xin0;
    const __half*   kern  = z ? nullptr : kern0;
    const uint32_t* wt    = z ? wt1 : wt0;
    const float*    bias  = z ? bias1 : bias0;
    const float*    resid = z ? resid1 : resid0;
    __half2*        outh  = z ? outh1 : outh0;
    float*          outf  = z ? outf1 : outf0;

    const int tid  = threadIdx.x;
    const int warp = tid >> 5;
    const int lane = tid & 31;
    const int gq   = lane >> 2;
    const int tq   = lane & 3;
    const int wr   = warp >> 2;
    const int c0   = (warp & 3) << 5;
    const int row_out = h0 + wr;

    int pixc[2][2];
    pixc[0][0] = c0 + gq;      pixc[0][1] = c0 + gq + 8;
    pixc[1][0] = c0 + 16 + gq; pixc[1][1] = c0 + 24 + gq;

    float acc[2][8][4];
#pragma unroll
    for (int mh = 0; mh < 2; mh++)
#pragma unroll
        for (int n = 0; n < 8; n++)
#pragma unroll
            for (int i = 0; i < 4; i++) acc[mh][n][i] = 0.f;

    const __half2* xb = xin + (size_t)bb * QPLANE;

    for (int p = 0; p < 9; p++) {
        const int dy = p / 3 - 1, dx = p % 3 - 1;
        const int row = row_out + dy;
        if (row < 0 || row >= Hk) continue;

        __half2 kv2[2][2];
        if (kern) {
            const __half* kb = kern + ((bb * 9 + p) * Hk + row_out) * Wk;
            kv2[0][0] = __half2half2(__ldg(kb + pixc[0][0]));
            kv2[0][1] = __half2half2(__ldg(kb + pixc[0][1]));
            kv2[1][0] = __half2half2(__ldg(kb + pixc[1][0]));
            kv2[1][1] = __half2half2(__ldg(kb + pixc[1][1]));
        }

        const __half2* xrow = xb + (size_t)(row * Wk) * 4 + tq;

#pragma unroll
        for (int kh2 = 0; kh2 < 2; kh2++) {
            const uint2* bw =
                (const uint2*)(wt + p * 2048 + kh2 * 1024) + lane;

#pragma unroll
            for (int kc = 0; kc < 2; kc++) {
                uint32_t f[2][4];
#pragma unroll
                for (int mh = 0; mh < 2; mh++)
#pragma unroll
                    for (int kk = 0; kk < 2; kk++)
#pragma unroll
                        for (int rr = 0; rr < 2; rr++) {
                            const int g = kh2 * 4 + kc * 2 + kk;
                            const int col = pixc[mh][rr] + dx;
                            const bool ok = (unsigned)col < 128u;
                            __half2 v = ok
                                ? __ldg(xrow + ((size_t)g * NPIX + col) * 4)
                                : __half2(__float2half2_rn(0.f));
                            if (kern) v = __hmul2(v, kv2[mh][rr]);
                            f[mh][rr + kk * 2] = *(uint32_t*)&v;
                        }

#pragma unroll
                for (int nc = 0; nc < 8; nc++) {
                    uint2 b = __ldg(bw + (kc * 8 + nc) * 32);
                    MMAF16(acc[0][nc], f[0][0], f[0][1], f[0][2], f[0][3],
                           b.x, b.y);
                    MMAF16(acc[1][nc], f[1][0], f[1][1], f[1][2], f[1][3],
                           b.x, b.y);
                }
            }
        }
    }

    // epilogue
    const int rowoff0 = row_out * Wk;
#pragma unroll
    for (int mh = 0; mh < 2; mh++) {
#pragma unroll
        for (int nc = 0; nc < 8; nc++) {
            int o0 = nc * 8 + tq * 2;
            float bv0 = __ldg(bias + o0);
            float bv1 = __ldg(bias + o0 + 1);
            float v00 = acc[mh][nc][0] + bv0;
            float v01 = acc[mh][nc][1] + bv1;
            float v10 = acc[mh][nc][2] + bv0;
            float v11 = acc[mh][nc][3] + bv1;
            if (do_relu) {
                v00 = fmaxf(v00, 0.f); v01 = fmaxf(v01, 0.f);
                v10 = fmaxf(v10, 0.f); v11 = fmaxf(v11, 0.f);
            }
            if (outh) {
                __half2* oh = outh + ((size_t)(bb * 8 + nc) * NPIX + rowoff0) * 4 + tq;
                float2 p0; p0.x = v00; p0.y = v01;
                float2 p1; p1.x = v10; p1.y = v11;
                oh[(size_t)pixc[mh][0] * 4] = __float22half2_rn(p0);
                oh[(size_t)pixc[mh][1] * 4] = __float22half2_rn(p1);
            }
            if (outf) {
                int i00 = (bb * Ck + o0) * NPIX + rowoff0 + pixc[mh][0];
                if (resid) {
                    v00 += resid[i00];
                    v01 += resid[i00 + NPIX];
                    v10 += resid[i00 + 8];
                    v11 += resid[i00 + NPIX + 8];
                }
                outf[i00] = v00;
                outf[i00 + NPIX] = v01;
                outf[i00 + 8] = v10;
                outf[i00 + NPIX + 8] = v11;
            }
        }
    }
}

// ---------------------------------------------------------------------------
extern "C" void kernel_launch(void* const* d_in, const int* in_sizes, int n_in,
                              void* d_out, int out_size) {
    const float* x      = (const float*)d_in[0];
    const float* edge   = (const float*)d_in[1];
    const float* w_pac1 = (const float*)d_in[2];
    const float* b_pac1 = (const float*)d_in[3];
    const float* w_pac2 = (const float*)d_in[4];
    const float* b_pac2 = (const float*)d_in[5];
    const float* w_e1   = (const float*)d_in[6];
    const float* b_e1   = (const float*)d_in[7];
    const float* w_e2   = (const float*)d_in[8];
    const float* b_e2   = (const float*)d_in[9];

    float* out_sr   = (float*)d_out;
    float* out_edge = out_sr + TENSOR;

    float *p_tmp_edge, *p_fields;
    __half* p_kern;
    __half2 *p_xh, *p_eh, *p_tsh, *p_teh;
    uint32_t* p_wpk;
    cudaGetSymbolAddress((void**)&p_tmp_edge, g_tmp_edge);
    cudaGetSymbolAddress((void**)&p_kern, g_kern);
    cudaGetSymbolAddress((void**)&p_fields, g_fields);
    cudaGetSymbolAddress((void**)&p_xh, g_xh);
    cudaGetSymbolAddress((void**)&p_eh, g_eh);
    cudaGetSymbolAddress((void**)&p_tsh, g_tsh);
    cudaGetSymbolAddress((void**)&p_teh, g_teh);
    cudaGetSymbolAddress((void**)&p_wpk, g_wpk);

    prep_weights<<<(4 * 9 * 2048 + 255) / 256, 256>>>(w_pac1, w_pac2, w_e1, w_e2);

    {
        dim3 sgrid((Bk * 8 * NPIX + 255) / 256, 2);
        split_kernel<<<sgrid, 256>>>(x, edge, p_xh, p_eh);
    }

    dim3 fgrid(Hk / 2, Bk);
    dim3 kgrid(Hk, Bk);
    dim3 cgrid(Hk / 2, Bk, 2);
    const int WS = 9 * 2048;

    // stage 1: kern(edge); z=0 pac(x) -> tsh, z=1 conv(edge) -> teh + fp32
    field_kernel<<<fgrid, 256>>>(edge, p_fields);
    kern_assemble_kernel<<<kgrid, 128>>>(p_fields, p_kern);
    conv3x3_hmma_kernel<<<cgrid, 256>>>(
        p_xh, p_kern, p_wpk + 0 * WS, b_pac1, nullptr, p_tsh, nullptr,
        p_eh,         p_wpk + 2 * WS, b_e1,   nullptr, p_teh, p_tmp_edge, 1);

    // stage 2: kern(tmp_edge); z=0 pac(tsh)+x -> out_sr, z=1 conv(teh)+edge
    field_kernel<<<fgrid, 256>>>(p_tmp_edge, p_fields);
    kern_assemble_kernel<<<kgrid, 128>>>(p_fields, p_kern);
    conv3x3_hmma_kernel<<<cgrid, 256>>>(
        p_tsh, p_kern, p_wpk + 1 * WS, b_pac2, x,    nullptr, out_sr,
        p_teh,         p_wpk + 3 * WS, b_e2,   edge, nullptr, out_edge, 0);
}